// round 3
// baseline (speedup 1.0000x reference)
#include <cuda_runtime.h>

// PIPNet fused gather + MLP:
//   out[p] = relu(concat(g1[il[p]], g2[ir[p]]) @ W1^T + b1) @ W2^T + b2
// P ~ 1e6 pairs, D=64, ED=128.
//
// R2 fix: indices are int32 (JAX x64-disabled silently downcasts the
// reference's astype(int64)). Also clamp gathered rows into [0,N) so a
// dtype surprise shows up as rel_err, not an illegal access.

#define TILE 128
#define NTHREADS 256

__device__ __forceinline__ unsigned long long pack2(float v) {
    unsigned long long r;
    asm("mov.b64 %0, {%1, %1};" : "=l"(r) : "f"(v));
    return r;
}

__device__ __forceinline__ void fma2(unsigned long long& acc,
                                     unsigned long long a,
                                     unsigned long long b) {
    asm("fma.rn.f32x2 %0, %1, %2, %0;" : "+l"(acc) : "l"(a), "l"(b));
}

__global__ __launch_bounds__(NTHREADS)
void pipnet_fused_kernel(const float* __restrict__ g1,
                         const float* __restrict__ g2,
                         const int* __restrict__ idxL,
                         const int* __restrict__ idxR,
                         const float* __restrict__ W1,
                         const float* __restrict__ b1,
                         const float* __restrict__ W2,
                         const float* __restrict__ b2,
                         float* __restrict__ out,
                         int P, int Nnodes)
{
    extern __shared__ float smem[];
    float* Xs = smem;           // [128 k][128 row]  (k-major)
    float* Ws = smem + 16384;   // [128 k][128 j]    (k-major, W1 transposed)

    const int tid = threadIdx.x;
    const long long base = (long long)blockIdx.x * TILE;

    // ---- Stage W1 transposed into smem: Ws[k*128 + j] = W1[j*128 + k] ----
    #pragma unroll
    for (int w = 0; w < 16; ++w) {
        int c = tid + NTHREADS * w;        // [0, 4096)
        int j  = c & 127;
        int k4 = c >> 7;                   // [0, 32)
        float4 v = *(const float4*)(W1 + j * 128 + k4 * 4);
        Ws[(4 * k4 + 0) * 128 + j] = v.x;
        Ws[(4 * k4 + 1) * 128 + j] = v.y;
        Ws[(4 * k4 + 2) * 128 + j] = v.z;
        Ws[(4 * k4 + 3) * 128 + j] = v.w;
    }

    // ---- Gather X tile: row r = pair (base+r), cols 0..63 g1, 64..127 g2 ----
    {
        int r = tid & 127;                 // row
        int h = tid >> 7;                  // half: 0 = left/g1, 1 = right/g2
        long long pair = base + r;
        if (pair >= P) pair = P - 1;       // clamp (results discarded later)
        int srcRow = h ? idxR[pair] : idxL[pair];
        if (srcRow < 0) srcRow = 0;
        if (srcRow >= Nnodes) srcRow = Nnodes - 1;
        const float* src = (h ? g2 : g1) + (long long)srcRow * 64;
        #pragma unroll
        for (int i = 0; i < 16; ++i) {
            float4 v = *(const float4*)(src + i * 4);
            int kb = h * 64 + i * 4;
            Xs[(kb + 0) * 128 + r] = v.x;
            Xs[(kb + 1) * 128 + r] = v.y;
            Xs[(kb + 2) * 128 + r] = v.z;
            Xs[(kb + 3) * 128 + r] = v.w;
        }
    }
    __syncthreads();

    // ---- Register-blocked GEMM: thread = 8 rows x 8 j, FFMA2 on row pairs ----
    const int tx = tid & 15;               // j group
    const int ty = tid >> 4;               // row group
    const int r0 = ty * 8;
    const int jA = tx * 4;                 // j chunk A: [jA, jA+3]
    const int jB = 64 + tx * 4;            // j chunk B: [jB, jB+3]

    unsigned long long acc[4][8];          // [row pair][j]
    #pragma unroll
    for (int a = 0; a < 4; ++a)
        #pragma unroll
        for (int b = 0; b < 8; ++b)
            acc[a][b] = 0ull;

    #pragma unroll 4
    for (int k = 0; k < 128; ++k) {
        const float* xrow = Xs + k * 128;
        const float* wrow = Ws + k * 128;
        ulonglong2 xa = *(const ulonglong2*)(xrow + r0);
        ulonglong2 xb = *(const ulonglong2*)(xrow + r0 + 4);
        unsigned long long xp0 = xa.x, xp1 = xa.y, xp2 = xb.x, xp3 = xb.y;
        float4 wa = *(const float4*)(wrow + jA);
        float4 wb = *(const float4*)(wrow + jB);
        unsigned long long wp[8];
        wp[0] = pack2(wa.x); wp[1] = pack2(wa.y);
        wp[2] = pack2(wa.z); wp[3] = pack2(wa.w);
        wp[4] = pack2(wb.x); wp[5] = pack2(wb.y);
        wp[6] = pack2(wb.z); wp[7] = pack2(wb.w);
        #pragma unroll
        for (int jj = 0; jj < 8; ++jj) {
            fma2(acc[0][jj], xp0, wp[jj]);
            fma2(acc[1][jj], xp1, wp[jj]);
            fma2(acc[2][jj], xp2, wp[jj]);
            fma2(acc[3][jj], xp3, wp[jj]);
        }
    }

    // ---- Epilogue: bias + ReLU + dot with W2 ----
    float b1v[8], w2v[8];
    #pragma unroll
    for (int q = 0; q < 4; ++q) {
        b1v[q]     = b1[jA + q];  w2v[q]     = W2[jA + q];
        b1v[4 + q] = b1[jB + q];  w2v[4 + q] = W2[jB + q];
    }

    float part[8];
    #pragma unroll
    for (int rr = 0; rr < 8; ++rr) part[rr] = 0.f;

    #pragma unroll
    for (int rp = 0; rp < 4; ++rp) {
        #pragma unroll
        for (int jj = 0; jj < 8; ++jj) {
            unsigned long long u = acc[rp][jj];
            float lo = __uint_as_float((unsigned int)(u & 0xffffffffull));
            float hi = __uint_as_float((unsigned int)(u >> 32));
            part[2 * rp]     += fmaxf(lo + b1v[jj], 0.f) * w2v[jj];
            part[2 * rp + 1] += fmaxf(hi + b1v[jj], 0.f) * w2v[jj];
        }
    }

    // ---- Cross-thread (tx) reduction via smem (stride 17) ----
    __syncthreads();                        // Xs region now dead; reuse it
    float* red = smem;                      // [128][17]
    #pragma unroll
    for (int rr = 0; rr < 8; ++rr)
        red[(r0 + rr) * 17 + tx] = part[rr];
    __syncthreads();

    if (tid < 128) {
        float s = b2[0];
        #pragma unroll
        for (int t = 0; t < 16; ++t)
            s += red[tid * 17 + t];
        long long p = base + tid;
        if (p < P) out[p] = s;
    }
}

extern "C" void kernel_launch(void* const* d_in, const int* in_sizes, int n_in,
                              void* d_out, int out_size) {
    const float* g1  = (const float*)d_in[0];   // graph1_x [N,64]
    const float* g2  = (const float*)d_in[1];   // graph2_x [N,64]
    const int*   il  = (const int*)d_in[2];     // idx_left  [P] int32
    const int*   ir  = (const int*)d_in[3];     // idx_right [P] int32
    const float* W1  = (const float*)d_in[4];   // [128,128]
    const float* b1  = (const float*)d_in[5];   // [128]
    const float* W2  = (const float*)d_in[6];   // [1,128]
    const float* b2  = (const float*)d_in[7];   // [1]
    float*       out = (float*)d_out;           // [P,1]

    int P = in_sizes[2];
    int Nnodes = in_sizes[0] / 64;
    int grid = (P + TILE - 1) / TILE;
    size_t smem_bytes = 2 * 128 * 128 * sizeof(float);  // 128 KB

    cudaFuncSetAttribute(pipnet_fused_kernel,
                         cudaFuncAttributeMaxDynamicSharedMemorySize,
                         (int)smem_bytes);
    pipnet_fused_kernel<<<grid, NTHREADS, smem_bytes>>>(
        g1, g2, il, ir, W1, b1, W2, b2, out, P, Nnodes);
}

// round 6
// speedup vs baseline: 1.6669x; 1.6669x over previous
#include <cuda_runtime.h>
#include <cuda_bf16.h>
#include <cstdint>

// PIPNet fused gather + MLP via mma.sync (HMMA) bf16-split.
//   out[p] = relu(concat(g1[il[p]], g2[ir[p]]) @ W1^T + b1) @ W2^T + b2
// Per CTA: M=128 pairs, N=128 hidden, K=128.
// fp32 -> bf16 hi/lo; acc = hi*hi + lo*hi + hi*lo in fp32 (drop lo*lo).
// R5 fix: B (W1) is k-contiguous per n-row == col-major KxN, which matches
// the NON-trans ldmatrix fragment for mma row.col. R4 wrongly used .trans.

#define TILE 128
#define NTHREADS 256

// smem layout (bytes): 128x128 bf16 tiles, row stride 256B,
// 16B chunks xor-swizzled by (row&7) for conflict-free ldmatrix/STS.
#define SM_A_HI 0
#define SM_A_LO 32768
#define SM_B_HI 65536
#define SM_B_LO 98304
#define SM_B1   131072
#define SM_W2   131584
#define SM_RED  132096
#define SMEM_TOTAL (132096 + 1024 + 128)

static __device__ __forceinline__ uint32_t smem_u32(const void* p) {
    uint32_t a;
    asm("{ .reg .u64 t; cvta.to.shared.u64 t, %1; cvt.u32.u64 %0, t; }"
        : "=r"(a) : "l"(p));
    return a;
}

// Byte offset into a tile: row-major, 256B rows, swizzled 16B chunks.
static __device__ __forceinline__ uint32_t tile_off(int row, int chunk) {
    return (uint32_t)row * 256u + (uint32_t)((chunk ^ (row & 7)) * 16);
}

static __device__ __forceinline__ void ldsm_x4(uint32_t* r, uint32_t addr) {
    asm volatile("ldmatrix.sync.aligned.m8n8.x4.shared.b16 {%0,%1,%2,%3}, [%4];"
                 : "=r"(r[0]), "=r"(r[1]), "=r"(r[2]), "=r"(r[3]) : "r"(addr));
}
static __device__ __forceinline__ void mma_bf16(float* c, const uint32_t* a,
                                                uint32_t b0, uint32_t b1) {
    asm volatile("mma.sync.aligned.m16n8k16.row.col.f32.bf16.bf16.f32 "
                 "{%0,%1,%2,%3}, {%4,%5,%6,%7}, {%8,%9}, {%0,%1,%2,%3};"
                 : "+f"(c[0]), "+f"(c[1]), "+f"(c[2]), "+f"(c[3])
                 : "r"(a[0]), "r"(a[1]), "r"(a[2]), "r"(a[3]), "r"(b0), "r"(b1));
}

// Split 8 fp32 into bf16 hi and lo (residual) 16B vectors.
static __device__ __forceinline__ void split8(const float* src, uint4& hi, uint4& lo) {
    __nv_bfloat16 h[8], l[8];
    #pragma unroll
    for (int q = 0; q < 8; ++q) {
        float x = src[q];
        h[q] = __float2bfloat16_rn(x);
        l[q] = __float2bfloat16_rn(x - __bfloat162float(h[q]));
    }
    hi = *(const uint4*)h;
    lo = *(const uint4*)l;
}

__global__ __launch_bounds__(NTHREADS)
void pipnet_hmma_kernel(const float* __restrict__ g1,
                        const float* __restrict__ g2,
                        const int* __restrict__ idxL,
                        const int* __restrict__ idxR,
                        const float* __restrict__ W1,
                        const float* __restrict__ b1,
                        const float* __restrict__ W2,
                        const float* __restrict__ b2,
                        float* __restrict__ out,
                        int P, int Nnodes)
{
    extern __shared__ char smem[];
    const uint32_t sbase = smem_u32(smem);
    const int tid = threadIdx.x;
    const int wid = tid >> 5;
    const int lid = tid & 31;
    const long long base = (long long)blockIdx.x * TILE;

    // ---- Stage b1 / W2 ----
    if (tid < 128) {
        *(float*)(smem + SM_B1 + tid * 4) = b1[tid];
        *(float*)(smem + SM_W2 + tid * 4) = W2[tid];
    }

    // ---- Gather X rows, split hi/lo, store swizzled ----
    {
        int r = tid & 127;                 // tile row (pair)
        int h = tid >> 7;                  // 0: left/g1, 1: right/g2
        long long pair = base + r;
        if (pair >= P) pair = P - 1;
        int srcRow = h ? idxR[pair] : idxL[pair];
        if (srcRow < 0) srcRow = 0;
        if (srcRow >= Nnodes) srcRow = Nnodes - 1;
        const float* src = (h ? g2 : g1) + (long long)srcRow * 64;
        #pragma unroll
        for (int i = 0; i < 8; ++i) {      // 8 chunks of 8 cols in this half
            uint4 hi, lo;
            split8(src + i * 8, hi, lo);
            uint32_t off = tile_off(r, h * 8 + i);
            *(uint4*)(smem + SM_A_HI + off) = hi;
            *(uint4*)(smem + SM_A_LO + off) = lo;
        }
    }

    // ---- Stage W1 split (B[n][k] = W1[n][k]: k-contiguous = col-major KxN) ----
    #pragma unroll
    for (int it = 0; it < 8; ++it) {
        int t = tid + NTHREADS * it;       // 0..2047
        int row = t >> 4;                  // n
        int chunk = t & 15;                // 8-col chunk
        uint4 hi, lo;
        split8(W1 + row * 128 + chunk * 8, hi, lo);
        uint32_t off = tile_off(row, chunk);
        *(uint4*)(smem + SM_B_HI + off) = hi;
        *(uint4*)(smem + SM_B_LO + off) = lo;
    }
    __syncthreads();

    // ---- HMMA mainloop: warp = 32m x 64n; 3 passes (hiA*hiB, loA*hiB, hiA*loB) ----
    const int m_base = (wid >> 1) * 32;
    const int nb = wid & 1;
    const int n_base = nb * 64;
    const int gl = lid & 7;
    const int grp = lid >> 3;

    float acc[2][8][4];
    #pragma unroll
    for (int a = 0; a < 2; ++a)
        #pragma unroll
        for (int c = 0; c < 8; ++c)
            #pragma unroll
            for (int q = 0; q < 4; ++q) acc[a][c][q] = 0.f;

    const uint32_t aBases[3] = { sbase + SM_A_HI, sbase + SM_A_LO, sbase + SM_A_HI };
    const uint32_t bBases[3] = { sbase + SM_B_HI, sbase + SM_B_HI, sbase + SM_B_LO };

    #pragma unroll
    for (int pass = 0; pass < 3; ++pass) {
        uint32_t aB = aBases[pass];
        uint32_t bB = bBases[pass];
        #pragma unroll
        for (int ks = 0; ks < 8; ++ks) {
            int kc = ks * 2;
            // A frags: 2 subtiles of 16 rows (non-trans; A row-major m x k)
            uint32_t afr[2][4];
            #pragma unroll
            for (int mt = 0; mt < 2; ++mt) {
                int row = m_base + mt * 16 + (grp & 1) * 8 + gl;
                int chunk = kc + (grp >> 1);
                ldsm_x4(afr[mt], aB + tile_off(row, chunk));
            }
            // B frags: NON-trans x4 -> reg j = mat j
            //   mat0: n 0-7  of pr, k 0-7   -> b0 of n-chunk pr*2
            //   mat1: n 0-7  of pr, k 8-15  -> b1 of n-chunk pr*2
            //   mat2: n 8-15 of pr, k 0-7   -> b0 of n-chunk pr*2+1
            //   mat3: n 8-15 of pr, k 8-15  -> b1 of n-chunk pr*2+1
            uint32_t bf0[8], bf1[8];
            #pragma unroll
            for (int pr = 0; pr < 4; ++pr) {
                int row = n_base + pr * 16 + (grp >> 1) * 8 + gl;
                int chunk = kc + (grp & 1);
                uint32_t r[4];
                ldsm_x4(r, bB + tile_off(row, chunk));
                bf0[pr * 2]     = r[0];
                bf1[pr * 2]     = r[1];
                bf0[pr * 2 + 1] = r[2];
                bf1[pr * 2 + 1] = r[3];
            }
            #pragma unroll
            for (int mt = 0; mt < 2; ++mt)
                #pragma unroll
                for (int c = 0; c < 8; ++c)
                    mma_bf16(acc[mt][c], afr[mt], bf0[c], bf1[c]);
        }
    }

    // ---- Epilogue: bias + ReLU + W2 dot from accumulators ----
    const float* s_b1 = (const float*)(smem + SM_B1);
    const float* s_w2 = (const float*)(smem + SM_W2);
    float* red = (float*)(smem + SM_RED);
    const int q2 = (lid & 3) * 2;

    float b1v[8][2], w2v[8][2];
    #pragma unroll
    for (int c = 0; c < 8; ++c) {
        int n = n_base + c * 8 + q2;
        b1v[c][0] = s_b1[n];     b1v[c][1] = s_b1[n + 1];
        w2v[c][0] = s_w2[n];     w2v[c][1] = s_w2[n + 1];
    }

    #pragma unroll
    for (int mt = 0; mt < 2; ++mt) {
        float pa = 0.f, pb = 0.f;   // rows (l>>2) and (l>>2)+8 of this 16-row tile
        #pragma unroll
        for (int c = 0; c < 8; ++c) {
            pa += fmaxf(acc[mt][c][0] + b1v[c][0], 0.f) * w2v[c][0]
                + fmaxf(acc[mt][c][1] + b1v[c][1], 0.f) * w2v[c][1];
            pb += fmaxf(acc[mt][c][2] + b1v[c][0], 0.f) * w2v[c][0]
                + fmaxf(acc[mt][c][3] + b1v[c][1], 0.f) * w2v[c][1];
        }
        pa += __shfl_xor_sync(0xffffffffu, pa, 1);
        pa += __shfl_xor_sync(0xffffffffu, pa, 2);
        pb += __shfl_xor_sync(0xffffffffu, pb, 1);
        pb += __shfl_xor_sync(0xffffffffu, pb, 2);
        if ((lid & 3) == 0) {
            int ra = m_base + mt * 16 + (lid >> 2);
            red[ra * 2 + nb] = pa;
            red[(ra + 8) * 2 + nb] = pb;
        }
    }
    __syncthreads();

    if (tid < 128) {
        float s = red[tid * 2] + red[tid * 2 + 1] + b2[0];
        long long p = base + tid;
        if (p < P) out[p] = s;
    }
}

extern "C" void kernel_launch(void* const* d_in, const int* in_sizes, int n_in,
                              void* d_out, int out_size) {
    const float* g1  = (const float*)d_in[0];   // graph1_x [N,64]
    const float* g2  = (const float*)d_in[1];   // graph2_x [N,64]
    const int*   il  = (const int*)d_in[2];     // idx_left  [P] int32
    const int*   ir  = (const int*)d_in[3];     // idx_right [P] int32
    const float* W1  = (const float*)d_in[4];   // [128,128]
    const float* b1  = (const float*)d_in[5];   // [128]
    const float* W2  = (const float*)d_in[6];   // [1,128]
    const float* b2  = (const float*)d_in[7];   // [1]
    float*       out = (float*)d_out;           // [P,1]

    int P = in_sizes[2];
    int Nnodes = in_sizes[0] / 64;
    int grid = (P + TILE - 1) / TILE;

    cudaFuncSetAttribute(pipnet_hmma_kernel,
                         cudaFuncAttributeMaxDynamicSharedMemorySize, SMEM_TOTAL);
    pipnet_hmma_kernel<<<grid, NTHREADS, SMEM_TOTAL>>>(
        g1, g2, il, ir, W1, b1, W2, b2, out, P, Nnodes);
}